// round 10
// baseline (speedup 1.0000x reference)
#include <cuda_runtime.h>
#include <math.h>

// Problem constants (fixed by the reference)
#define F_IN 503
#define CC   32
#define MAXN 100000
#define MAXE 3200000
#define KT   32       // k-tile
#define GT   128      // GEMM threads per block
#define GROWS 256     // rows per GEMM block (2 per thread)
#define NEG  0.2f

// ---------------- scratch (static __device__ arrays; allocation-free) -------
__device__ float g_xl[(size_t)MAXN * CC];     // transformed node features [N,32]
__device__ float g_asrc[MAXN];
__device__ float g_adst[MAXN];
__device__ int   g_deg[MAXN];                 // in-degree (real edges only)
__device__ int   g_scan[MAXN];
__device__ int   g_rowptr[MAXN + 1];
__device__ int   g_cursor[MAXN];
__device__ int   g_bsum[256];
__device__ int   g_boff[256];
__device__ unsigned long long g_csr[MAXE + MAXN];   // packed (src:int, w:float)
__device__ float g_hw[MAXN];                  // h[v] . Ww
__device__ float g_scalars[4];   // [0]=sum(ew), [1]=k_edge, [2]=mean(ew)

// ---------------- init: deg=0, scalars --------------------------------------
__global__ void k_init(const float* __restrict__ W_edge,
                       const float* __restrict__ att_edge, int nN) {
    int i = blockIdx.x * blockDim.x + threadIdx.x;
    if (i < nN) g_deg[i] = 0;
    if (i == 0) {
        g_scalars[0] = 0.f;
        float ke = 0.f;
        #pragma unroll
        for (int c = 0; c < CC; c++) ke += W_edge[c] * att_edge[c];
        g_scalars[1] = ke;   // a_edge = k_edge * edge_weight
    }
}

// ---------------- degree count + edge_weight sum (vectorized) ---------------
__global__ void k_deg_mean(const int* __restrict__ ei,
                           const float* __restrict__ ew, int nE) {
    int tid = threadIdx.x;
    float sum = 0.f;
    int nq = nE >> 2;
    for (int q = blockIdx.x * blockDim.x + tid; q < nq;
         q += gridDim.x * blockDim.x) {
        int4 d4 = ((const int4*)(ei + nE))[q];
        float4 w4 = ((const float4*)ew)[q];
        atomicAdd(&g_deg[d4.x], 1);
        atomicAdd(&g_deg[d4.y], 1);
        atomicAdd(&g_deg[d4.z], 1);
        atomicAdd(&g_deg[d4.w], 1);
        sum += w4.x + w4.y + w4.z + w4.w;
    }
    int base = nq << 2;
    for (int i = base + blockIdx.x * blockDim.x + tid; i < nE;
         i += gridDim.x * blockDim.x) {
        atomicAdd(&g_deg[ei[nE + i]], 1);
        sum += ew[i];
    }
    __shared__ float red[256];
    red[tid] = sum;
    __syncthreads();
    for (int s = 128; s > 0; s >>= 1) {
        if (tid < s) red[tid] += red[tid + s];
        __syncthreads();
    }
    if (tid == 0) atomicAdd(&g_scalars[0], red[0]);
}

// ---------------- GEMM: xl = x @ W^T, fused a_src/a_dst ---------------------
// 2 rows per thread: the 8 broadcast LDS.128 W-loads per k-step feed 32
// FFMA2 instead of 16, halving the smem-pipe pressure per FLOP.
__global__ void __launch_bounds__(GT, 2)
k_gemm(const float* __restrict__ x, const float* __restrict__ W,
       const float* __restrict__ att_src, const float* __restrict__ att_dst,
       int nN) {
    extern __shared__ unsigned char sm[];
    unsigned long long* Wp = (unsigned long long*)sm;            // 512*16 pairs
    float* xs = (float*)(sm + (size_t)512 * 16 * 8);             // GROWS*(KT+1)

    int tid = threadIdx.x;
    // pack W (zero-padded to 512 k's): Wp[k*16+c2] = (W[2c2,k], W[2c2+1,k])
    for (int i = tid; i < 512 * 16; i += GT) {
        int k = i >> 4, c2 = i & 15;
        float lo = 0.f, hi = 0.f;
        if (k < F_IN) {
            lo = W[(2 * c2) * F_IN + k];
            hi = W[(2 * c2 + 1) * F_IN + k];
        }
        unsigned long long p;
        asm("mov.b64 %0, {%1, %2};" : "=l"(p) : "f"(lo), "f"(hi));
        Wp[i] = p;
    }

    int rbase = blockIdx.x * GROWS;
    unsigned long long acc0[16], acc1[16];
    #pragma unroll
    for (int j = 0; j < 16; j++) { acc0[j] = 0ull; acc1[j] = 0ull; }

    #pragma unroll 1
    for (int kt = 0; kt < 512; kt += KT) {
        __syncthreads();
        // stage GROWS x KT tile with GT threads (coalesced LDG, padded STS)
        {
            int k = tid & 31;
            int r0 = tid >> 5;                 // 4 rows per pass
            #pragma unroll 8
            for (int rr = 0; rr < GROWS / 4; rr++) {
                int lrow = r0 + (rr << 2);
                int gr = rbase + lrow;
                int gk = kt + k;
                float v = 0.f;
                if (gr < nN && gk < F_IN) v = x[(size_t)gr * F_IN + gk];
                xs[lrow * (KT + 1) + k] = v;
            }
        }
        __syncthreads();
        const float* xr0 = &xs[tid * (KT + 1)];
        const float* xr1 = &xs[(tid + GT) * (KT + 1)];
        #pragma unroll 8
        for (int k = 0; k < KT; k++) {
            float xv0 = xr0[k];
            float xv1 = xr1[k];
            unsigned long long xx0, xx1;
            asm("mov.b64 %0, {%1, %1};" : "=l"(xx0) : "f"(xv0));
            asm("mov.b64 %0, {%1, %1};" : "=l"(xx1) : "f"(xv1));
            const ulonglong2* wr = (const ulonglong2*)&Wp[(kt + k) * 16];
            #pragma unroll
            for (int j = 0; j < 8; j++) {
                ulonglong2 wp = wr[j];
                asm("fma.rn.f32x2 %0, %1, %2, %0;" : "+l"(acc0[2 * j])     : "l"(xx0), "l"(wp.x));
                asm("fma.rn.f32x2 %0, %1, %2, %0;" : "+l"(acc0[2 * j + 1]) : "l"(xx0), "l"(wp.y));
                asm("fma.rn.f32x2 %0, %1, %2, %0;" : "+l"(acc1[2 * j])     : "l"(xx1), "l"(wp.x));
                asm("fma.rn.f32x2 %0, %1, %2, %0;" : "+l"(acc1[2 * j + 1]) : "l"(xx1), "l"(wp.y));
            }
        }
    }

    int row0 = rbase + tid;
    int row1 = rbase + tid + GT;
    if (row0 < nN) {
        float as = 0.f, ad = 0.f;
        unsigned long long* dst = (unsigned long long*)(g_xl + (size_t)row0 * CC);
        #pragma unroll
        for (int j = 0; j < 16; j++) {
            dst[j] = acc0[j];
            float lo, hi;
            asm("mov.b64 {%0, %1}, %2;" : "=f"(lo), "=f"(hi) : "l"(acc0[j]));
            as += lo * att_src[2 * j] + hi * att_src[2 * j + 1];
            ad += lo * att_dst[2 * j] + hi * att_dst[2 * j + 1];
        }
        g_asrc[row0] = as;
        g_adst[row0] = ad;
    }
    if (row1 < nN) {
        float as = 0.f, ad = 0.f;
        unsigned long long* dst = (unsigned long long*)(g_xl + (size_t)row1 * CC);
        #pragma unroll
        for (int j = 0; j < 16; j++) {
            dst[j] = acc1[j];
            float lo, hi;
            asm("mov.b64 {%0, %1}, %2;" : "=f"(lo), "=f"(hi) : "l"(acc1[j]));
            as += lo * att_src[2 * j] + hi * att_src[2 * j + 1];
            ad += lo * att_dst[2 * j] + hi * att_dst[2 * j + 1];
        }
        g_asrc[row1] = as;
        g_adst[row1] = ad;
    }
}

// ---------------- scan (exclusive prefix of deg -> rowptr) ------------------
__global__ void k_scan1(int nN) {
    __shared__ int sh[1024];
    int tid = threadIdx.x;
    int i = blockIdx.x * 1024 + tid;
    int v = (i < nN) ? g_deg[i] : 0;
    sh[tid] = v;
    __syncthreads();
    for (int off = 1; off < 1024; off <<= 1) {
        int t = (tid >= off) ? sh[tid - off] : 0;
        __syncthreads();
        sh[tid] += t;
        __syncthreads();
    }
    if (i < nN) g_scan[i] = sh[tid];
    if (tid == 1023) g_bsum[blockIdx.x] = sh[1023];
}

__global__ void k_scan2(int nb, int nE) {
    int run = 0;
    for (int b = 0; b < nb; b++) {
        int t = g_bsum[b];
        g_boff[b] = run;
        run += t;
    }
    g_scalars[2] = g_scalars[0] / (float)nE;   // mean edge weight
}

// rowptr[i] = edge_scan[i] + i (self-loop slot per node, pre-written here).
__global__ void k_scan3(int nN, int nE) {
    int i = blockIdx.x * blockDim.x + threadIdx.x;
    if (i < nN) {
        int ex = g_scan[i] - g_deg[i] + g_boff[i >> 10] + i;
        g_rowptr[i] = ex;
        g_cursor[i] = ex + 1;
        unsigned long long e = (unsigned long long)(unsigned)i |
            ((unsigned long long)__float_as_uint(g_scalars[2]) << 32);
        g_csr[ex] = e;
    }
    if (i == 0) g_rowptr[nN] = nN + nE;
}

// ---------------- fill CSR with packed (src, edge_weight) -------------------
__global__ void k_fill(const int* __restrict__ ei, const float* __restrict__ ew,
                       int nE) {
    int i = blockIdx.x * blockDim.x + threadIdx.x;
    if (i >= nE) return;
    int s = ei[i];
    int d = ei[nE + i];
    float w = ew[i];
    int pos = atomicAdd(&g_cursor[d], 1);
    unsigned long long e = (unsigned long long)(unsigned)s |
                           ((unsigned long long)__float_as_uint(w) << 32);
    g_csr[pos] = e;
}

// ---------------- gather: softmax-aggregate + fused heads -------------------
__global__ void __launch_bounds__(256)
k_gather(const float* __restrict__ bias_conv,
         const float* __restrict__ Wb, const float* __restrict__ bb,
         const float* __restrict__ Ww, const float* __restrict__ mask,
         float* __restrict__ out, int nN, int nE) {
    int warp = (blockIdx.x * blockDim.x + threadIdx.x) >> 5;
    int lane = threadIdx.x & 31;
    if (warp >= nN) return;
    int beg = g_rowptr[warp];
    int end = g_rowptr[warp + 1];
    float ad = g_adst[warp];
    float ke = g_scalars[1];
    float acc = 0.f, den = 0.f;

    int i = beg;
    for (; i + 4 <= end; i += 4) {
        unsigned long long e0 = g_csr[i];
        unsigned long long e1 = g_csr[i + 1];
        unsigned long long e2 = g_csr[i + 2];
        unsigned long long e3 = g_csr[i + 3];
        int s0 = (int)(unsigned)e0, s1 = (int)(unsigned)e1;
        int s2 = (int)(unsigned)e2, s3 = (int)(unsigned)e3;
        float v0 = g_xl[(size_t)s0 * CC + lane];
        float v1 = g_xl[(size_t)s1 * CC + lane];
        float v2 = g_xl[(size_t)s2 * CC + lane];
        float v3 = g_xl[(size_t)s3 * CC + lane];
        float as0 = g_asrc[s0], as1 = g_asrc[s1];
        float as2 = g_asrc[s2], as3 = g_asrc[s3];
        float a0 = fmaf(ke, __uint_as_float((unsigned)(e0 >> 32)), as0 + ad);
        float a1 = fmaf(ke, __uint_as_float((unsigned)(e1 >> 32)), as1 + ad);
        float a2 = fmaf(ke, __uint_as_float((unsigned)(e2 >> 32)), as2 + ad);
        float a3 = fmaf(ke, __uint_as_float((unsigned)(e3 >> 32)), as3 + ad);
        a0 = (a0 > 0.f) ? a0 : NEG * a0;
        a1 = (a1 > 0.f) ? a1 : NEG * a1;
        a2 = (a2 > 0.f) ? a2 : NEG * a2;
        a3 = (a3 > 0.f) ? a3 : NEG * a3;
        float x0 = __expf(a0), x1 = __expf(a1);
        float x2 = __expf(a2), x3 = __expf(a3);
        den += x0 + x1 + x2 + x3;
        acc = fmaf(x0, v0, acc);
        acc = fmaf(x1, v1, acc);
        acc = fmaf(x2, v2, acc);
        acc = fmaf(x3, v3, acc);
    }
    for (; i < end; i++) {
        unsigned long long e = g_csr[i];
        int s = (int)(unsigned)e;
        float v = g_xl[(size_t)s * CC + lane];
        float a = fmaf(ke, __uint_as_float((unsigned)(e >> 32)), g_asrc[s] + ad);
        a = (a > 0.f) ? a : NEG * a;
        float ex = __expf(a);
        den += ex;
        acc = fmaf(ex, v, acc);
    }

    float h = acc / den + bias_conv[lane];
    h = fmaxf(h, 0.f);
    float bsum = h * Wb[lane];
    float wsum = h * Ww[lane];
    #pragma unroll
    for (int o = 16; o > 0; o >>= 1) {
        bsum += __shfl_xor_sync(0xFFFFFFFFu, bsum, o);
        wsum += __shfl_xor_sync(0xFFFFFFFFu, wsum, o);
    }
    if (lane == 0) {
        g_hw[warp] = wsum;
        out[nE + warp] = (bsum + bb[0]) * mask[warp];
    }
}

// ---------------- edge output: 0.5*(hw[s]+hw[d]) + bw (vectorized) ---------
__global__ void k_edge(const int* __restrict__ ei, const float* __restrict__ bw,
                       float* __restrict__ out, int nE) {
    int q = blockIdx.x * blockDim.x + threadIdx.x;
    int nq = nE >> 2;
    float b = bw[0];
    if (q < nq) {
        int4 s4 = ((const int4*)ei)[q];
        int4 d4 = ((const int4*)(ei + nE))[q];
        float4 o;
        o.x = 0.5f * (g_hw[s4.x] + g_hw[d4.x]) + b;
        o.y = 0.5f * (g_hw[s4.y] + g_hw[d4.y]) + b;
        o.z = 0.5f * (g_hw[s4.z] + g_hw[d4.z]) + b;
        o.w = 0.5f * (g_hw[s4.w] + g_hw[d4.w]) + b;
        ((float4*)out)[q] = o;
    }
    if (q < (nE & 3)) {
        int idx = (nq << 2) + q;
        out[idx] = 0.5f * (g_hw[ei[idx]] + g_hw[ei[nE + idx]]) + b;
    }
}

// ---------------- launch ----------------------------------------------------
extern "C" void kernel_launch(void* const* d_in, const int* in_sizes, int n_in,
                              void* d_out, int out_size) {
    const float* x         = (const float*)d_in[0];
    const int*   ei        = (const int*)d_in[1];
    const float* ew        = (const float*)d_in[2];
    const float* mask      = (const float*)d_in[3];
    const float* W_src     = (const float*)d_in[4];
    const float* att_src   = (const float*)d_in[5];
    const float* att_dst   = (const float*)d_in[6];
    const float* att_edge  = (const float*)d_in[7];
    const float* W_edge    = (const float*)d_in[8];
    const float* bias_conv = (const float*)d_in[9];
    const float* Wb        = (const float*)d_in[10];
    const float* bb        = (const float*)d_in[11];
    const float* Ww        = (const float*)d_in[12];
    const float* bw        = (const float*)d_in[13];
    float* out = (float*)d_out;

    int nN = in_sizes[3];            // input_mask: [N,1]
    int nE = in_sizes[2];            // edge_weight: [E,1]

    const int smem = 512 * 16 * 8 + GROWS * (KT + 1) * 4;   // 99328 B
    cudaFuncSetAttribute((const void*)k_gemm,
                         cudaFuncAttributeMaxDynamicSharedMemorySize, smem);

    int nb = (nN + 1023) / 1024;
    // Order keeps k_gemm in the ncu-profiled slot (4th launch).
    k_init<<<(nN + 255) / 256, 256>>>(W_edge, att_edge, nN);
    k_deg_mean<<<2048, 256>>>(ei, ew, nE);
    k_scan1<<<nb, 1024>>>(nN);
    k_gemm<<<(nN + GROWS - 1) / GROWS, GT, smem>>>(x, W_src, att_src, att_dst, nN);
    k_scan2<<<1, 1>>>(nb, nE);
    k_scan3<<<(nN + 255) / 256, 256>>>(nN, nE);
    k_fill<<<(nE + 255) / 256, 256>>>(ei, ew, nE);
    k_gather<<<(nN + 7) / 8, 256>>>(bias_conv, Wb, bb, Ww, mask, out, nN, nE);
    k_edge<<<((nE >> 2) + 255) / 256, 256>>>(ei, bw, out, nE);
}

// round 11
// speedup vs baseline: 1.2210x; 1.2210x over previous
#include <cuda_runtime.h>
#include <math.h>

// Problem constants (fixed by the reference)
#define F_IN 503
#define CC   32
#define MAXN 100000
#define MAXE 3200000
#define KT   32       // k-tile
#define GT   256      // GEMM threads per block
#define GROWS 256     // rows per GEMM block
#define NEG  0.2f

// ---------------- scratch (static __device__ arrays; allocation-free) -------
__device__ float g_xl[(size_t)MAXN * CC];     // transformed node features [N,32]
__device__ float g_asrc[MAXN];
__device__ float g_adst[MAXN];
__device__ int   g_deg[MAXN];                 // in-degree (real edges only)
__device__ int   g_scan[MAXN];
__device__ int   g_rowptr[MAXN + 1];
__device__ int   g_cursor[MAXN];
__device__ int   g_bsum[256];
__device__ int   g_boff[256];
__device__ unsigned long long g_csr[MAXE + MAXN];   // packed (src:int, w:float)
__device__ float g_hw[MAXN];                  // h[v] . Ww
__device__ float g_scalars[4];   // [0]=sum(ew), [1]=k_edge, [2]=mean(ew)

// ---------------- init: deg=0, scalars --------------------------------------
__global__ void k_init(const float* __restrict__ W_edge,
                       const float* __restrict__ att_edge, int nN) {
    int i = blockIdx.x * blockDim.x + threadIdx.x;
    if (i < nN) g_deg[i] = 0;
    if (i == 0) {
        g_scalars[0] = 0.f;
        float ke = 0.f;
        #pragma unroll
        for (int c = 0; c < CC; c++) ke += W_edge[c] * att_edge[c];
        g_scalars[1] = ke;   // a_edge = k_edge * edge_weight
    }
}

// ---------------- degree count + edge_weight sum (vectorized) ---------------
__global__ void k_deg_mean(const int* __restrict__ ei,
                           const float* __restrict__ ew, int nE) {
    int tid = threadIdx.x;
    float sum = 0.f;
    int nq = nE >> 2;
    for (int q = blockIdx.x * blockDim.x + tid; q < nq;
         q += gridDim.x * blockDim.x) {
        int4 d4 = ((const int4*)(ei + nE))[q];
        float4 w4 = ((const float4*)ew)[q];
        atomicAdd(&g_deg[d4.x], 1);
        atomicAdd(&g_deg[d4.y], 1);
        atomicAdd(&g_deg[d4.z], 1);
        atomicAdd(&g_deg[d4.w], 1);
        sum += w4.x + w4.y + w4.z + w4.w;
    }
    int base = nq << 2;
    for (int i = base + blockIdx.x * blockDim.x + tid; i < nE;
         i += gridDim.x * blockDim.x) {
        atomicAdd(&g_deg[ei[nE + i]], 1);
        sum += ew[i];
    }
    __shared__ float red[256];
    red[tid] = sum;
    __syncthreads();
    for (int s = 128; s > 0; s >>= 1) {
        if (tid < s) red[tid] += red[tid + s];
        __syncthreads();
    }
    if (tid == 0) atomicAdd(&g_scalars[0], red[0]);
}

// ---------------- GEMM: xl = x @ W^T, fused a_src/a_dst ---------------------
// Thread = 4 rows x 8 channels. Per k-step: 4 LDS.32 (x) + 2 LDS.128 (W)
// feed 16 FFMA2 -> 6:16 LDS:FFMA2 ratio with only 32 accumulator regs.
// Channel-group partials for a_src/a_dst reduced via shfl_xor.
__global__ void __launch_bounds__(GT, 2)
k_gemm(const float* __restrict__ x, const float* __restrict__ W,
       const float* __restrict__ att_src, const float* __restrict__ att_dst,
       int nN) {
    extern __shared__ unsigned char sm[];
    unsigned long long* Wp = (unsigned long long*)sm;            // 512*16 pairs
    float* xs = (float*)(sm + (size_t)512 * 16 * 8);             // GROWS*(KT+1)

    int tid = threadIdx.x;
    // pack W (zero-padded to 512 k's): Wp[k*16+c2] = (W[2c2,k], W[2c2+1,k])
    for (int i = tid; i < 512 * 16; i += GT) {
        int k = i >> 4, c2 = i & 15;
        float lo = 0.f, hi = 0.f;
        if (k < F_IN) {
            lo = W[(2 * c2) * F_IN + k];
            hi = W[(2 * c2 + 1) * F_IN + k];
        }
        unsigned long long p;
        asm("mov.b64 %0, {%1, %2};" : "=l"(p) : "f"(lo), "f"(hi));
        Wp[i] = p;
    }

    int cg = tid & 3;          // channel group: pairs cg*4 .. cg*4+3
    int rg = tid >> 2;         // row group: rows rg*4 .. rg*4+3
    int rbase = blockIdx.x * GROWS;

    unsigned long long acc[16];   // [pair j][row r] = acc[j*4+r]
    #pragma unroll
    for (int j = 0; j < 16; j++) acc[j] = 0ull;

    #pragma unroll 1
    for (int kt = 0; kt < 512; kt += KT) {
        __syncthreads();
        // stage GROWS x KT tile (coalesced LDG, conflict-free padded STS)
        {
            int k = tid & 31;
            int r0 = tid >> 5;                 // 8 rows per pass
            #pragma unroll 8
            for (int rr = 0; rr < GROWS / 8; rr++) {
                int lrow = r0 + (rr << 3);
                int gr = rbase + lrow;
                int gk = kt + k;
                float v = 0.f;
                if (gr < nN && gk < F_IN) v = x[(size_t)gr * F_IN + gk];
                xs[lrow * (KT + 1) + k] = v;
            }
        }
        __syncthreads();
        const float* xr = &xs[(rg * 4) * (KT + 1)];
        #pragma unroll 8
        for (int k = 0; k < KT; k++) {
            float x0 = xr[0 * (KT + 1) + k];
            float x1 = xr[1 * (KT + 1) + k];
            float x2 = xr[2 * (KT + 1) + k];
            float x3 = xr[3 * (KT + 1) + k];
            unsigned long long xx0, xx1, xx2, xx3;
            asm("mov.b64 %0, {%1, %1};" : "=l"(xx0) : "f"(x0));
            asm("mov.b64 %0, {%1, %1};" : "=l"(xx1) : "f"(x1));
            asm("mov.b64 %0, {%1, %1};" : "=l"(xx2) : "f"(x2));
            asm("mov.b64 %0, {%1, %1};" : "=l"(xx3) : "f"(x3));
            const ulonglong2* wr =
                (const ulonglong2*)&Wp[(kt + k) * 16 + cg * 4];
            ulonglong2 wa = wr[0];   // pairs j=0,1
            ulonglong2 wb = wr[1];   // pairs j=2,3
            asm("fma.rn.f32x2 %0, %1, %2, %0;" : "+l"(acc[0])  : "l"(xx0), "l"(wa.x));
            asm("fma.rn.f32x2 %0, %1, %2, %0;" : "+l"(acc[1])  : "l"(xx1), "l"(wa.x));
            asm("fma.rn.f32x2 %0, %1, %2, %0;" : "+l"(acc[2])  : "l"(xx2), "l"(wa.x));
            asm("fma.rn.f32x2 %0, %1, %2, %0;" : "+l"(acc[3])  : "l"(xx3), "l"(wa.x));
            asm("fma.rn.f32x2 %0, %1, %2, %0;" : "+l"(acc[4])  : "l"(xx0), "l"(wa.y));
            asm("fma.rn.f32x2 %0, %1, %2, %0;" : "+l"(acc[5])  : "l"(xx1), "l"(wa.y));
            asm("fma.rn.f32x2 %0, %1, %2, %0;" : "+l"(acc[6])  : "l"(xx2), "l"(wa.y));
            asm("fma.rn.f32x2 %0, %1, %2, %0;" : "+l"(acc[7])  : "l"(xx3), "l"(wa.y));
            asm("fma.rn.f32x2 %0, %1, %2, %0;" : "+l"(acc[8])  : "l"(xx0), "l"(wb.x));
            asm("fma.rn.f32x2 %0, %1, %2, %0;" : "+l"(acc[9])  : "l"(xx1), "l"(wb.x));
            asm("fma.rn.f32x2 %0, %1, %2, %0;" : "+l"(acc[10]) : "l"(xx2), "l"(wb.x));
            asm("fma.rn.f32x2 %0, %1, %2, %0;" : "+l"(acc[11]) : "l"(xx3), "l"(wb.x));
            asm("fma.rn.f32x2 %0, %1, %2, %0;" : "+l"(acc[12]) : "l"(xx0), "l"(wb.y));
            asm("fma.rn.f32x2 %0, %1, %2, %0;" : "+l"(acc[13]) : "l"(xx1), "l"(wb.y));
            asm("fma.rn.f32x2 %0, %1, %2, %0;" : "+l"(acc[14]) : "l"(xx2), "l"(wb.y));
            asm("fma.rn.f32x2 %0, %1, %2, %0;" : "+l"(acc[15]) : "l"(xx3), "l"(wb.y));
        }
    }

    // epilogue: store 4x8 block; reduce a_src/a_dst partials across the 4
    // channel-group lanes (bits 0..1 of the lane id).
    float asr[4] = {0.f, 0.f, 0.f, 0.f};
    float adr[4] = {0.f, 0.f, 0.f, 0.f};
    #pragma unroll
    for (int j = 0; j < 4; j++) {
        int ch = cg * 8 + 2 * j;
        float aslo = att_src[ch], ashi = att_src[ch + 1];
        float adlo = att_dst[ch], adhi = att_dst[ch + 1];
        #pragma unroll
        for (int r = 0; r < 4; r++) {
            unsigned long long a = acc[j * 4 + r];
            float lo, hi;
            asm("mov.b64 {%0, %1}, %2;" : "=f"(lo), "=f"(hi) : "l"(a));
            int row = rbase + rg * 4 + r;
            if (row < nN)
                *(unsigned long long*)(g_xl + (size_t)row * CC + ch) = a;
            asr[r] += lo * aslo + hi * ashi;
            adr[r] += lo * adlo + hi * adhi;
        }
    }
    #pragma unroll
    for (int r = 0; r < 4; r++) {
        asr[r] += __shfl_xor_sync(0xFFFFFFFFu, asr[r], 1);
        asr[r] += __shfl_xor_sync(0xFFFFFFFFu, asr[r], 2);
        adr[r] += __shfl_xor_sync(0xFFFFFFFFu, adr[r], 1);
        adr[r] += __shfl_xor_sync(0xFFFFFFFFu, adr[r], 2);
        int row = rbase + rg * 4 + r;
        if (cg == 0 && row < nN) {
            g_asrc[row] = asr[r];
            g_adst[row] = adr[r];
        }
    }
}

// ---------------- scan (exclusive prefix of deg -> rowptr) ------------------
__global__ void k_scan1(int nN) {
    __shared__ int sh[1024];
    int tid = threadIdx.x;
    int i = blockIdx.x * 1024 + tid;
    int v = (i < nN) ? g_deg[i] : 0;
    sh[tid] = v;
    __syncthreads();
    for (int off = 1; off < 1024; off <<= 1) {
        int t = (tid >= off) ? sh[tid - off] : 0;
        __syncthreads();
        sh[tid] += t;
        __syncthreads();
    }
    if (i < nN) g_scan[i] = sh[tid];
    if (tid == 1023) g_bsum[blockIdx.x] = sh[1023];
}

__global__ void k_scan2(int nb, int nE) {
    int run = 0;
    for (int b = 0; b < nb; b++) {
        int t = g_bsum[b];
        g_boff[b] = run;
        run += t;
    }
    g_scalars[2] = g_scalars[0] / (float)nE;   // mean edge weight
}

// rowptr[i] = edge_scan[i] + i (self-loop slot per node, pre-written here).
__global__ void k_scan3(int nN, int nE) {
    int i = blockIdx.x * blockDim.x + threadIdx.x;
    if (i < nN) {
        int ex = g_scan[i] - g_deg[i] + g_boff[i >> 10] + i;
        g_rowptr[i] = ex;
        g_cursor[i] = ex + 1;
        unsigned long long e = (unsigned long long)(unsigned)i |
            ((unsigned long long)__float_as_uint(g_scalars[2]) << 32);
        g_csr[ex] = e;
    }
    if (i == 0) g_rowptr[nN] = nN + nE;
}

// ---------------- fill CSR with packed (src, edge_weight) -------------------
__global__ void k_fill(const int* __restrict__ ei, const float* __restrict__ ew,
                       int nE) {
    int i = blockIdx.x * blockDim.x + threadIdx.x;
    if (i >= nE) return;
    int s = ei[i];
    int d = ei[nE + i];
    float w = ew[i];
    int pos = atomicAdd(&g_cursor[d], 1);
    unsigned long long e = (unsigned long long)(unsigned)s |
                           ((unsigned long long)__float_as_uint(w) << 32);
    g_csr[pos] = e;
}

// ---------------- gather: softmax-aggregate + fused heads -------------------
__global__ void __launch_bounds__(256)
k_gather(const float* __restrict__ bias_conv,
         const float* __restrict__ Wb, const float* __restrict__ bb,
         const float* __restrict__ Ww, const float* __restrict__ mask,
         float* __restrict__ out, int nN, int nE) {
    int warp = (blockIdx.x * blockDim.x + threadIdx.x) >> 5;
    int lane = threadIdx.x & 31;
    if (warp >= nN) return;
    int beg = g_rowptr[warp];
    int end = g_rowptr[warp + 1];
    float ad = g_adst[warp];
    float ke = g_scalars[1];
    float acc = 0.f, den = 0.f;

    int i = beg;
    for (; i + 4 <= end; i += 4) {
        unsigned long long e0 = g_csr[i];
        unsigned long long e1 = g_csr[i + 1];
        unsigned long long e2 = g_csr[i + 2];
        unsigned long long e3 = g_csr[i + 3];
        int s0 = (int)(unsigned)e0, s1 = (int)(unsigned)e1;
        int s2 = (int)(unsigned)e2, s3 = (int)(unsigned)e3;
        float v0 = g_xl[(size_t)s0 * CC + lane];
        float v1 = g_xl[(size_t)s1 * CC + lane];
        float v2 = g_xl[(size_t)s2 * CC + lane];
        float v3 = g_xl[(size_t)s3 * CC + lane];
        float as0 = g_asrc[s0], as1 = g_asrc[s1];
        float as2 = g_asrc[s2], as3 = g_asrc[s3];
        float a0 = fmaf(ke, __uint_as_float((unsigned)(e0 >> 32)), as0 + ad);
        float a1 = fmaf(ke, __uint_as_float((unsigned)(e1 >> 32)), as1 + ad);
        float a2 = fmaf(ke, __uint_as_float((unsigned)(e2 >> 32)), as2 + ad);
        float a3 = fmaf(ke, __uint_as_float((unsigned)(e3 >> 32)), as3 + ad);
        a0 = (a0 > 0.f) ? a0 : NEG * a0;
        a1 = (a1 > 0.f) ? a1 : NEG * a1;
        a2 = (a2 > 0.f) ? a2 : NEG * a2;
        a3 = (a3 > 0.f) ? a3 : NEG * a3;
        float x0 = __expf(a0), x1 = __expf(a1);
        float x2 = __expf(a2), x3 = __expf(a3);
        den += x0 + x1 + x2 + x3;
        acc = fmaf(x0, v0, acc);
        acc = fmaf(x1, v1, acc);
        acc = fmaf(x2, v2, acc);
        acc = fmaf(x3, v3, acc);
    }
    for (; i < end; i++) {
        unsigned long long e = g_csr[i];
        int s = (int)(unsigned)e;
        float v = g_xl[(size_t)s * CC + lane];
        float a = fmaf(ke, __uint_as_float((unsigned)(e >> 32)), g_asrc[s] + ad);
        a = (a > 0.f) ? a : NEG * a;
        float ex = __expf(a);
        den += ex;
        acc = fmaf(ex, v, acc);
    }

    float h = acc / den + bias_conv[lane];
    h = fmaxf(h, 0.f);
    float bsum = h * Wb[lane];
    float wsum = h * Ww[lane];
    #pragma unroll
    for (int o = 16; o > 0; o >>= 1) {
        bsum += __shfl_xor_sync(0xFFFFFFFFu, bsum, o);
        wsum += __shfl_xor_sync(0xFFFFFFFFu, wsum, o);
    }
    if (lane == 0) {
        g_hw[warp] = wsum;
        out[nE + warp] = (bsum + bb[0]) * mask[warp];
    }
}

// ---------------- edge output: 0.5*(hw[s]+hw[d]) + bw (vectorized) ---------
__global__ void k_edge(const int* __restrict__ ei, const float* __restrict__ bw,
                       float* __restrict__ out, int nE) {
    int q = blockIdx.x * blockDim.x + threadIdx.x;
    int nq = nE >> 2;
    float b = bw[0];
    if (q < nq) {
        int4 s4 = ((const int4*)ei)[q];
        int4 d4 = ((const int4*)(ei + nE))[q];
        float4 o;
        o.x = 0.5f * (g_hw[s4.x] + g_hw[d4.x]) + b;
        o.y = 0.5f * (g_hw[s4.y] + g_hw[d4.y]) + b;
        o.z = 0.5f * (g_hw[s4.z] + g_hw[d4.z]) + b;
        o.w = 0.5f * (g_hw[s4.w] + g_hw[d4.w]) + b;
        ((float4*)out)[q] = o;
    }
    if (q < (nE & 3)) {
        int idx = (nq << 2) + q;
        out[idx] = 0.5f * (g_hw[ei[idx]] + g_hw[ei[nE + idx]]) + b;
    }
}

// ---------------- launch ----------------------------------------------------
extern "C" void kernel_launch(void* const* d_in, const int* in_sizes, int n_in,
                              void* d_out, int out_size) {
    const float* x         = (const float*)d_in[0];
    const int*   ei        = (const int*)d_in[1];
    const float* ew        = (const float*)d_in[2];
    const float* mask      = (const float*)d_in[3];
    const float* W_src     = (const float*)d_in[4];
    const float* att_src   = (const float*)d_in[5];
    const float* att_dst   = (const float*)d_in[6];
    const float* att_edge  = (const float*)d_in[7];
    const float* W_edge    = (const float*)d_in[8];
    const float* bias_conv = (const float*)d_in[9];
    const float* Wb        = (const float*)d_in[10];
    const float* bb        = (const float*)d_in[11];
    const float* Ww        = (const float*)d_in[12];
    const float* bw        = (const float*)d_in[13];
    float* out = (float*)d_out;

    int nN = in_sizes[3];            // input_mask: [N,1]
    int nE = in_sizes[2];            // edge_weight: [E,1]

    const int smem = 512 * 16 * 8 + GROWS * (KT + 1) * 4;   // 99328 B
    cudaFuncSetAttribute((const void*)k_gemm,
                         cudaFuncAttributeMaxDynamicSharedMemorySize, smem);

    int nb = (nN + 1023) / 1024;
    // Order keeps k_gemm in the ncu-profiled slot (4th launch).
    k_init<<<(nN + 255) / 256, 256>>>(W_edge, att_edge, nN);
    k_deg_mean<<<2048, 256>>>(ei, ew, nE);
    k_scan1<<<nb, 1024>>>(nN);
    k_gemm<<<(nN + GROWS - 1) / GROWS, GT, smem>>>(x, W_src, att_src, att_dst, nN);
    k_scan2<<<1, 1>>>(nb, nE);
    k_scan3<<<(nN + 255) / 256, 256>>>(nN, nE);
    k_fill<<<(nE + 255) / 256, 256>>>(ei, ew, nE);
    k_gather<<<(nN + 7) / 8, 256>>>(bias_conv, Wb, bb, Ww, mask, out, nN, nE);
    k_edge<<<((nE >> 2) + 255) / 256, 256>>>(ei, bw, out, nE);
}

// round 12
// speedup vs baseline: 1.2756x; 1.0447x over previous
#include <cuda_runtime.h>
#include <math.h>

// Problem constants (fixed by the reference)
#define F_IN 503
#define CC   32
#define MAXN 100000
#define MAXE 3200000
#define KT   32       // k-tile
#define GT   256      // GEMM threads per block
#define GROWS 128     // rows per GEMM block (2 per thread)
#define XST  34       // x-tile row stride in floats (8B aligned, conflict-free)
#define NEG  0.2f

// ---------------- scratch (static __device__ arrays; allocation-free) -------
__device__ float g_xl[(size_t)MAXN * CC];     // transformed node features [N,32]
__device__ float g_asrc[MAXN];
__device__ float g_adst[MAXN];
__device__ int   g_deg[MAXN];                 // in-degree (real edges only)
__device__ int   g_scan[MAXN];
__device__ int   g_rowptr[MAXN + 1];
__device__ int   g_cursor[MAXN];
__device__ int   g_bsum[256];
__device__ int   g_boff[256];
__device__ unsigned long long g_csr[MAXE + MAXN];   // packed (src:int, w:float)
__device__ float g_hw[MAXN];                  // h[v] . Ww
__device__ float g_scalars[4];   // [0]=sum(ew), [1]=k_edge, [2]=mean(ew)

// ---------------- init: deg=0, scalars --------------------------------------
__global__ void k_init(const float* __restrict__ W_edge,
                       const float* __restrict__ att_edge, int nN) {
    int i = blockIdx.x * blockDim.x + threadIdx.x;
    if (i < nN) g_deg[i] = 0;
    if (i == 0) {
        g_scalars[0] = 0.f;
        float ke = 0.f;
        #pragma unroll
        for (int c = 0; c < CC; c++) ke += W_edge[c] * att_edge[c];
        g_scalars[1] = ke;   // a_edge = k_edge * edge_weight
    }
}

// ---------------- degree count + edge_weight sum (vectorized) ---------------
__global__ void k_deg_mean(const int* __restrict__ ei,
                           const float* __restrict__ ew, int nE) {
    int tid = threadIdx.x;
    float sum = 0.f;
    int nq = nE >> 2;
    for (int q = blockIdx.x * blockDim.x + tid; q < nq;
         q += gridDim.x * blockDim.x) {
        int4 d4 = ((const int4*)(ei + nE))[q];
        float4 w4 = ((const float4*)ew)[q];
        atomicAdd(&g_deg[d4.x], 1);
        atomicAdd(&g_deg[d4.y], 1);
        atomicAdd(&g_deg[d4.z], 1);
        atomicAdd(&g_deg[d4.w], 1);
        sum += w4.x + w4.y + w4.z + w4.w;
    }
    int base = nq << 2;
    for (int i = base + blockIdx.x * blockDim.x + tid; i < nE;
         i += gridDim.x * blockDim.x) {
        atomicAdd(&g_deg[ei[nE + i]], 1);
        sum += ew[i];
    }
    __shared__ float red[256];
    red[tid] = sum;
    __syncthreads();
    for (int s = 128; s > 0; s >>= 1) {
        if (tid < s) red[tid] += red[tid + s];
        __syncthreads();
    }
    if (tid == 0) atomicAdd(&g_scalars[0], red[0]);
}

// ---------------- GEMM: xl = x @ W^T, fused a_src/a_dst ---------------------
// Thread = 2 rows x 8 channels (8 f32x2 accumulators = 16 regs). W is tiled
// through smem per k-tile (4KB slice; W is L1/L2-resident so reloads are
// cheap), keeping smem at ~21.5KB and regs <=64 so 4 blocks/SM fit
// (32 warps, ~42% occ) to hide LDS/barrier latency.
__global__ void __launch_bounds__(GT, 4)
k_gemm(const float* __restrict__ x, const float* __restrict__ W,
       const float* __restrict__ att_src, const float* __restrict__ att_dst,
       int nN) {
    __shared__ float xs[GROWS * XST];                 // 17408 B
    __shared__ unsigned long long Wp[KT * 16];        // 4096 B

    int tid = threadIdx.x;
    int cg = tid & 3;          // channel group: pairs cg*4 .. cg*4+3
    int rg = tid >> 2;         // row group: rows rg*2, rg*2+1
    int rbase = blockIdx.x * GROWS;

    unsigned long long acc[8];   // [pair j 0..3][row r 0..1] = acc[j*2+r]
    #pragma unroll
    for (int j = 0; j < 8; j++) acc[j] = 0ull;

    #pragma unroll 1
    for (int kt = 0; kt < 512; kt += KT) {
        __syncthreads();
        // stage W k-slice: Wp[k*16+c2] = (W[2c2, kt+k], W[2c2+1, kt+k])
        #pragma unroll
        for (int t = tid; t < KT * 16; t += GT) {
            int k = t >> 4, c2 = t & 15;
            int gk = kt + k;
            float lo = 0.f, hi = 0.f;
            if (gk < F_IN) {
                lo = W[(2 * c2) * F_IN + gk];
                hi = W[(2 * c2 + 1) * F_IN + gk];
            }
            unsigned long long p;
            asm("mov.b64 %0, {%1, %2};" : "=l"(p) : "f"(lo), "f"(hi));
            Wp[t] = p;
        }
        // stage x tile: GROWS x KT (coalesced LDG, padded STS)
        {
            int k = tid & 31;
            int r0 = tid >> 5;                 // 8 rows per pass
            #pragma unroll
            for (int rr = 0; rr < GROWS / 8; rr++) {
                int lrow = r0 + (rr << 3);
                int gr = rbase + lrow;
                int gk = kt + k;
                float v = 0.f;
                if (gr < nN && gk < F_IN) v = x[(size_t)gr * F_IN + gk];
                xs[lrow * XST + k] = v;
            }
        }
        __syncthreads();
        const float2* xr0 = (const float2*)&xs[(rg * 2) * XST];
        const float2* xr1 = (const float2*)&xs[(rg * 2 + 1) * XST];
        #pragma unroll
        for (int k2 = 0; k2 < KT / 2; k2++) {
            float2 xa = xr0[k2];    // rows' k = 2k2, 2k2+1
            float2 xb = xr1[k2];
            unsigned long long x0a, x0b, x1a, x1b;
            asm("mov.b64 %0, {%1, %1};" : "=l"(x0a) : "f"(xa.x));
            asm("mov.b64 %0, {%1, %1};" : "=l"(x0b) : "f"(xa.y));
            asm("mov.b64 %0, {%1, %1};" : "=l"(x1a) : "f"(xb.x));
            asm("mov.b64 %0, {%1, %1};" : "=l"(x1b) : "f"(xb.y));
            const ulonglong2* w0 =
                (const ulonglong2*)&Wp[(2 * k2) * 16 + cg * 4];
            const ulonglong2* w1 =
                (const ulonglong2*)&Wp[(2 * k2 + 1) * 16 + cg * 4];
            ulonglong2 wa0 = w0[0], wb0 = w0[1];
            ulonglong2 wa1 = w1[0], wb1 = w1[1];
            // k = 2k2
            asm("fma.rn.f32x2 %0, %1, %2, %0;" : "+l"(acc[0]) : "l"(x0a), "l"(wa0.x));
            asm("fma.rn.f32x2 %0, %1, %2, %0;" : "+l"(acc[1]) : "l"(x1a), "l"(wa0.x));
            asm("fma.rn.f32x2 %0, %1, %2, %0;" : "+l"(acc[2]) : "l"(x0a), "l"(wa0.y));
            asm("fma.rn.f32x2 %0, %1, %2, %0;" : "+l"(acc[3]) : "l"(x1a), "l"(wa0.y));
            asm("fma.rn.f32x2 %0, %1, %2, %0;" : "+l"(acc[4]) : "l"(x0a), "l"(wb0.x));
            asm("fma.rn.f32x2 %0, %1, %2, %0;" : "+l"(acc[5]) : "l"(x1a), "l"(wb0.x));
            asm("fma.rn.f32x2 %0, %1, %2, %0;" : "+l"(acc[6]) : "l"(x0a), "l"(wb0.y));
            asm("fma.rn.f32x2 %0, %1, %2, %0;" : "+l"(acc[7]) : "l"(x1a), "l"(wb0.y));
            // k = 2k2+1
            asm("fma.rn.f32x2 %0, %1, %2, %0;" : "+l"(acc[0]) : "l"(x0b), "l"(wa1.x));
            asm("fma.rn.f32x2 %0, %1, %2, %0;" : "+l"(acc[1]) : "l"(x1b), "l"(wa1.x));
            asm("fma.rn.f32x2 %0, %1, %2, %0;" : "+l"(acc[2]) : "l"(x0b), "l"(wa1.y));
            asm("fma.rn.f32x2 %0, %1, %2, %0;" : "+l"(acc[3]) : "l"(x1b), "l"(wa1.y));
            asm("fma.rn.f32x2 %0, %1, %2, %0;" : "+l"(acc[4]) : "l"(x0b), "l"(wb1.x));
            asm("fma.rn.f32x2 %0, %1, %2, %0;" : "+l"(acc[5]) : "l"(x1b), "l"(wb1.x));
            asm("fma.rn.f32x2 %0, %1, %2, %0;" : "+l"(acc[6]) : "l"(x0b), "l"(wb1.y));
            asm("fma.rn.f32x2 %0, %1, %2, %0;" : "+l"(acc[7]) : "l"(x1b), "l"(wb1.y));
        }
    }

    // epilogue: store 2x8 block; reduce a_src/a_dst partials across the 4
    // channel-group lanes (lane bits 0..1).
    float asr[2] = {0.f, 0.f};
    float adr[2] = {0.f, 0.f};
    #pragma unroll
    for (int j = 0; j < 4; j++) {
        int ch = cg * 8 + 2 * j;
        float aslo = att_src[ch], ashi = att_src[ch + 1];
        float adlo = att_dst[ch], adhi = att_dst[ch + 1];
        #pragma unroll
        for (int r = 0; r < 2; r++) {
            unsigned long long a = acc[j * 2 + r];
            float lo, hi;
            asm("mov.b64 {%0, %1}, %2;" : "=f"(lo), "=f"(hi) : "l"(a));
            int row = rbase + rg * 2 + r;
            if (row < nN)
                *(unsigned long long*)(g_xl + (size_t)row * CC + ch) = a;
            asr[r] += lo * aslo + hi * ashi;
            adr[r] += lo * adlo + hi * adhi;
        }
    }
    #pragma unroll
    for (int r = 0; r < 2; r++) {
        asr[r] += __shfl_xor_sync(0xFFFFFFFFu, asr[r], 1);
        asr[r] += __shfl_xor_sync(0xFFFFFFFFu, asr[r], 2);
        adr[r] += __shfl_xor_sync(0xFFFFFFFFu, adr[r], 1);
        adr[r] += __shfl_xor_sync(0xFFFFFFFFu, adr[r], 2);
        int row = rbase + rg * 2 + r;
        if (cg == 0 && row < nN) {
            g_asrc[row] = asr[r];
            g_adst[row] = adr[r];
        }
    }
}

// ---------------- scan (exclusive prefix of deg -> rowptr) ------------------
__global__ void k_scan1(int nN) {
    __shared__ int sh[1024];
    int tid = threadIdx.x;
    int i = blockIdx.x * 1024 + tid;
    int v = (i < nN) ? g_deg[i] : 0;
    sh[tid] = v;
    __syncthreads();
    for (int off = 1; off < 1024; off <<= 1) {
        int t = (tid >= off) ? sh[tid - off] : 0;
        __syncthreads();
        sh[tid] += t;
        __syncthreads();
    }
    if (i < nN) g_scan[i] = sh[tid];
    if (tid == 1023) g_bsum[blockIdx.x] = sh[1023];
}

__global__ void k_scan2(int nb, int nE) {
    int run = 0;
    for (int b = 0; b < nb; b++) {
        int t = g_bsum[b];
        g_boff[b] = run;
        run += t;
    }
    g_scalars[2] = g_scalars[0] / (float)nE;   // mean edge weight
}

// rowptr[i] = edge_scan[i] + i (self-loop slot per node, pre-written here).
__global__ void k_scan3(int nN, int nE) {
    int i = blockIdx.x * blockDim.x + threadIdx.x;
    if (i < nN) {
        int ex = g_scan[i] - g_deg[i] + g_boff[i >> 10] + i;
        g_rowptr[i] = ex;
        g_cursor[i] = ex + 1;
        unsigned long long e = (unsigned long long)(unsigned)i |
            ((unsigned long long)__float_as_uint(g_scalars[2]) << 32);
        g_csr[ex] = e;
    }
    if (i == 0) g_rowptr[nN] = nN + nE;
}

// ---------------- fill CSR with packed (src, edge_weight) -------------------
__global__ void k_fill(const int* __restrict__ ei, const float* __restrict__ ew,
                       int nE) {
    int i = blockIdx.x * blockDim.x + threadIdx.x;
    if (i >= nE) return;
    int s = ei[i];
    int d = ei[nE + i];
    float w = ew[i];
    int pos = atomicAdd(&g_cursor[d], 1);
    unsigned long long e = (unsigned long long)(unsigned)s |
                           ((unsigned long long)__float_as_uint(w) << 32);
    g_csr[pos] = e;
}

// ---------------- gather: softmax-aggregate + fused heads -------------------
__global__ void __launch_bounds__(256)
k_gather(const float* __restrict__ bias_conv,
         const float* __restrict__ Wb, const float* __restrict__ bb,
         const float* __restrict__ Ww, const float* __restrict__ mask,
         float* __restrict__ out, int nN, int nE) {
    int warp = (blockIdx.x * blockDim.x + threadIdx.x) >> 5;
    int lane = threadIdx.x & 31;
    if (warp >= nN) return;
    int beg = g_rowptr[warp];
    int end = g_rowptr[warp + 1];
    float ad = g_adst[warp];
    float ke = g_scalars[1];
    float acc = 0.f, den = 0.f;

    int i = beg;
    for (; i + 4 <= end; i += 4) {
        unsigned long long e0 = g_csr[i];
        unsigned long long e1 = g_csr[i + 1];
        unsigned long long e2 = g_csr[i + 2];
        unsigned long long e3 = g_csr[i + 3];
        int s0 = (int)(unsigned)e0, s1 = (int)(unsigned)e1;
        int s2 = (int)(unsigned)e2, s3 = (int)(unsigned)e3;
        float v0 = g_xl[(size_t)s0 * CC + lane];
        float v1 = g_xl[(size_t)s1 * CC + lane];
        float v2 = g_xl[(size_t)s2 * CC + lane];
        float v3 = g_xl[(size_t)s3 * CC + lane];
        float as0 = g_asrc[s0], as1 = g_asrc[s1];
        float as2 = g_asrc[s2], as3 = g_asrc[s3];
        float a0 = fmaf(ke, __uint_as_float((unsigned)(e0 >> 32)), as0 + ad);
        float a1 = fmaf(ke, __uint_as_float((unsigned)(e1 >> 32)), as1 + ad);
        float a2 = fmaf(ke, __uint_as_float((unsigned)(e2 >> 32)), as2 + ad);
        float a3 = fmaf(ke, __uint_as_float((unsigned)(e3 >> 32)), as3 + ad);
        a0 = (a0 > 0.f) ? a0 : NEG * a0;
        a1 = (a1 > 0.f) ? a1 : NEG * a1;
        a2 = (a2 > 0.f) ? a2 : NEG * a2;
        a3 = (a3 > 0.f) ? a3 : NEG * a3;
        float x0 = __expf(a0), x1 = __expf(a1);
        float x2 = __expf(a2), x3 = __expf(a3);
        den += x0 + x1 + x2 + x3;
        acc = fmaf(x0, v0, acc);
        acc = fmaf(x1, v1, acc);
        acc = fmaf(x2, v2, acc);
        acc = fmaf(x3, v3, acc);
    }
    for (; i < end; i++) {
        unsigned long long e = g_csr[i];
        int s = (int)(unsigned)e;
        float v = g_xl[(size_t)s * CC + lane];
        float a = fmaf(ke, __uint_as_float((unsigned)(e >> 32)), g_asrc[s] + ad);
        a = (a > 0.f) ? a : NEG * a;
        float ex = __expf(a);
        den += ex;
        acc = fmaf(ex, v, acc);
    }

    float h = acc / den + bias_conv[lane];
    h = fmaxf(h, 0.f);
    float bsum = h * Wb[lane];
    float wsum = h * Ww[lane];
    #pragma unroll
    for (int o = 16; o > 0; o >>= 1) {
        bsum += __shfl_xor_sync(0xFFFFFFFFu, bsum, o);
        wsum += __shfl_xor_sync(0xFFFFFFFFu, wsum, o);
    }
    if (lane == 0) {
        g_hw[warp] = wsum;
        out[nE + warp] = (bsum + bb[0]) * mask[warp];
    }
}

// ---------------- edge output: 0.5*(hw[s]+hw[d]) + bw (vectorized) ---------
__global__ void k_edge(const int* __restrict__ ei, const float* __restrict__ bw,
                       float* __restrict__ out, int nE) {
    int q = blockIdx.x * blockDim.x + threadIdx.x;
    int nq = nE >> 2;
    float b = bw[0];
    if (q < nq) {
        int4 s4 = ((const int4*)ei)[q];
        int4 d4 = ((const int4*)(ei + nE))[q];
        float4 o;
        o.x = 0.5f * (g_hw[s4.x] + g_hw[d4.x]) + b;
        o.y = 0.5f * (g_hw[s4.y] + g_hw[d4.y]) + b;
        o.z = 0.5f * (g_hw[s4.z] + g_hw[d4.z]) + b;
        o.w = 0.5f * (g_hw[s4.w] + g_hw[d4.w]) + b;
        ((float4*)out)[q] = o;
    }
    if (q < (nE & 3)) {
        int idx = (nq << 2) + q;
        out[idx] = 0.5f * (g_hw[ei[idx]] + g_hw[ei[nE + idx]]) + b;
    }
}

// ---------------- launch ----------------------------------------------------
extern "C" void kernel_launch(void* const* d_in, const int* in_sizes, int n_in,
                              void* d_out, int out_size) {
    const float* x         = (const float*)d_in[0];
    const int*   ei        = (const int*)d_in[1];
    const float* ew        = (const float*)d_in[2];
    const float* mask      = (const float*)d_in[3];
    const float* W_src     = (const float*)d_in[4];
    const float* att_src   = (const float*)d_in[5];
    const float* att_dst   = (const float*)d_in[6];
    const float* att_edge  = (const float*)d_in[7];
    const float* W_edge    = (const float*)d_in[8];
    const float* bias_conv = (const float*)d_in[9];
    const float* Wb        = (const float*)d_in[10];
    const float* bb        = (const float*)d_in[11];
    const float* Ww        = (const float*)d_in[12];
    const float* bw        = (const float*)d_in[13];
    float* out = (float*)d_out;

    int nN = in_sizes[3];            // input_mask: [N,1]
    int nE = in_sizes[2];            // edge_weight: [E,1]

    int nb = (nN + 1023) / 1024;
    // Order keeps k_gemm in the ncu-profiled slot (4th launch).
    k_init<<<(nN + 255) / 256, 256>>>(W_edge, att_edge, nN);
    k_deg_mean<<<2048, 256>>>(ei, ew, nE);
    k_scan1<<<nb, 1024>>>(nN);
    k_gemm<<<(nN + GROWS - 1) / GROWS, GT>>>(x, W_src, att_src, att_dst, nN);
    k_scan2<<<1, 1>>>(nb, nE);
    k_scan3<<<(nN + 255) / 256, 256>>>(nN, nE);
    k_fill<<<(nE + 255) / 256, 256>>>(ei, ew, nE);
    k_gather<<<(nN + 7) / 8, 256>>>(bias_conv, Wb, bb, Ww, mask, out, nN, nE);
    k_edge<<<((nE >> 2) + 255) / 256, 256>>>(ei, bw, out, nE);
}

// round 13
// speedup vs baseline: 1.3447x; 1.0542x over previous
#include <cuda_runtime.h>
#include <cuda_bf16.h>
#include <math.h>

// Problem constants (fixed by the reference)
#define F_IN 503
#define CC   32
#define MAXN 100000
#define MAXE 3200000
#define GROWS 128     // rows per GEMM block (8 warps x m16)
#define KS   16       // k-step (one mma k-extent)
#define NEG  0.2f

// ---------------- scratch (static __device__ arrays; allocation-free) -------
__device__ float g_xl[(size_t)MAXN * CC];     // transformed node features [N,32]
__device__ float g_asrc[MAXN];
__device__ float g_adst[MAXN];
__device__ int   g_deg[MAXN];                 // in-degree (real edges only)
__device__ int   g_scan[MAXN];
__device__ int   g_rowptr[MAXN + 1];
__device__ int   g_cursor[MAXN];
__device__ int   g_bsum[256];
__device__ int   g_boff[256];
__device__ unsigned long long g_csr[MAXE + MAXN];   // packed (src:int, w:float)
__device__ float g_hw[MAXN];                  // h[v] . Ww
__device__ float g_scalars[4];   // [0]=sum(ew), [1]=k_edge, [2]=mean(ew)

// ---------------- init: deg=0, scalars --------------------------------------
__global__ void k_init(const float* __restrict__ W_edge,
                       const float* __restrict__ att_edge, int nN) {
    int i = blockIdx.x * blockDim.x + threadIdx.x;
    if (i < nN) g_deg[i] = 0;
    if (i == 0) {
        g_scalars[0] = 0.f;
        float ke = 0.f;
        #pragma unroll
        for (int c = 0; c < CC; c++) ke += W_edge[c] * att_edge[c];
        g_scalars[1] = ke;   // a_edge = k_edge * edge_weight
    }
}

// ---------------- degree count + edge_weight sum (vectorized) ---------------
__global__ void k_deg_mean(const int* __restrict__ ei,
                           const float* __restrict__ ew, int nE) {
    int tid = threadIdx.x;
    float sum = 0.f;
    int nq = nE >> 2;
    for (int q = blockIdx.x * blockDim.x + tid; q < nq;
         q += gridDim.x * blockDim.x) {
        int4 d4 = ((const int4*)(ei + nE))[q];
        float4 w4 = ((const float4*)ew)[q];
        atomicAdd(&g_deg[d4.x], 1);
        atomicAdd(&g_deg[d4.y], 1);
        atomicAdd(&g_deg[d4.z], 1);
        atomicAdd(&g_deg[d4.w], 1);
        sum += w4.x + w4.y + w4.z + w4.w;
    }
    int base = nq << 2;
    for (int i = base + blockIdx.x * blockDim.x + tid; i < nE;
         i += gridDim.x * blockDim.x) {
        atomicAdd(&g_deg[ei[nE + i]], 1);
        sum += ew[i];
    }
    __shared__ float red[256];
    red[tid] = sum;
    __syncthreads();
    for (int s = 128; s > 0; s >>= 1) {
        if (tid < s) red[tid] += red[tid + s];
        __syncthreads();
    }
    if (tid == 0) atomicAdd(&g_scalars[0], red[0]);
}

// ---------------- bf16 mma helper -------------------------------------------
__device__ __forceinline__ void mma16816(float* c,
                                         unsigned a0, unsigned a1,
                                         unsigned a2, unsigned a3,
                                         unsigned b0, unsigned b1) {
    asm volatile(
        "mma.sync.aligned.m16n8k16.row.col.f32.bf16.bf16.f32 "
        "{%0,%1,%2,%3}, {%4,%5,%6,%7}, {%8,%9}, {%0,%1,%2,%3};"
        : "+f"(c[0]), "+f"(c[1]), "+f"(c[2]), "+f"(c[3])
        : "r"(a0), "r"(a1), "r"(a2), "r"(a3), "r"(b0), "r"(b1));
}

// ---------------- GEMM: xl = x @ W^T via bf16-split tensor cores ------------
// x = xh + xl (bf16 split), W = Wh + Wl. xl@W ~= xh*Wh + xh*Wl + xl*Wh
// (dropped ll term ~2^-18 relative). Block = 128 rows, 8 warps x (m16,n32).
// Fragments loaded with direct LDS.32 (padded, conflict-free strides).
// a_src/a_dst fused in the epilogue via intra-quad shfl reduction.
__global__ void __launch_bounds__(256, 3)
k_gemm(const float* __restrict__ x, const float* __restrict__ W,
       const float* __restrict__ att_src, const float* __restrict__ att_dst,
       int nN) {
    __shared__ __nv_bfloat16 Ah[GROWS][24];   // stride 48B: conflict-free frag loads
    __shared__ __nv_bfloat16 Al[GROWS][24];
    __shared__ __nv_bfloat16 Bh[32][16];      // [n][k] slice of W
    __shared__ __nv_bfloat16 Bl[32][16];

    int tid = threadIdx.x;
    int lane = tid & 31;
    int wid = tid >> 5;
    int rbase = blockIdx.x * GROWS;

    float c[4][4];   // [ntile][frag]; ntile = channels nt*8..nt*8+7
    #pragma unroll
    for (int nt = 0; nt < 4; nt++)
        #pragma unroll
        for (int j = 0; j < 4; j++) c[nt][j] = 0.f;

    // staging coordinates
    int arow = tid >> 1;               // 0..127
    int akofs = (tid & 1) * 8;         // 0 or 8
    bool arok = (rbase + arow) < nN;
    const float* xrowp = x + (size_t)(rbase + arow) * F_IN;
    int bn = tid >> 3;                 // 0..31
    int bk = (tid & 7) * 2;            // 0,2,..,14

    // fragment coordinates (PTX m16n8k16 fragment mapping)
    int grp = lane >> 2;               // groupID
    int qid = lane & 3;                // thread-in-group
    int frow = wid * 16 + grp;         // A rows frow, frow+8
    int kp = qid * 2;                  // k within tile: kp, kp+1 (and +8)

    #pragma unroll 1
    for (int kt = 0; kt < 512; kt += KS) {
        __syncthreads();
        // ---- stage A (x tile 128 x 16, split hi/lo) ----
        {
            float v[8];
            #pragma unroll
            for (int j = 0; j < 8; j++) {
                int gk = kt + akofs + j;
                v[j] = (arok && gk < F_IN) ? xrowp[gk] : 0.f;
            }
            #pragma unroll
            for (int j = 0; j < 8; j += 2) {
                __nv_bfloat16 h0 = __float2bfloat16(v[j]);
                __nv_bfloat16 h1 = __float2bfloat16(v[j + 1]);
                float l0 = v[j]     - __bfloat162float(h0);
                float l1 = v[j + 1] - __bfloat162float(h1);
                *(__nv_bfloat162*)&Ah[arow][akofs + j] =
                    __halves2bfloat162(h0, h1);
                *(__nv_bfloat162*)&Al[arow][akofs + j] =
                    __halves2bfloat162(__float2bfloat16(l0),
                                       __float2bfloat16(l1));
            }
        }
        // ---- stage B (W slice 32 x 16, split hi/lo) ----
        {
            int gk = kt + bk;
            float w0 = (gk < F_IN)     ? W[bn * F_IN + gk]     : 0.f;
            float w1 = (gk + 1 < F_IN) ? W[bn * F_IN + gk + 1] : 0.f;
            __nv_bfloat16 h0 = __float2bfloat16(w0);
            __nv_bfloat16 h1 = __float2bfloat16(w1);
            float l0 = w0 - __bfloat162float(h0);
            float l1 = w1 - __bfloat162float(h1);
            *(__nv_bfloat162*)&Bh[bn][bk] = __halves2bfloat162(h0, h1);
            *(__nv_bfloat162*)&Bl[bn][bk] =
                __halves2bfloat162(__float2bfloat16(l0), __float2bfloat16(l1));
        }
        __syncthreads();

        // ---- fragments + mma ----
        unsigned ah0 = *(const unsigned*)&Ah[frow][kp];
        unsigned ah1 = *(const unsigned*)&Ah[frow + 8][kp];
        unsigned ah2 = *(const unsigned*)&Ah[frow][kp + 8];
        unsigned ah3 = *(const unsigned*)&Ah[frow + 8][kp + 8];
        unsigned al0 = *(const unsigned*)&Al[frow][kp];
        unsigned al1 = *(const unsigned*)&Al[frow + 8][kp];
        unsigned al2 = *(const unsigned*)&Al[frow][kp + 8];
        unsigned al3 = *(const unsigned*)&Al[frow + 8][kp + 8];
        #pragma unroll
        for (int nt = 0; nt < 4; nt++) {
            int n = nt * 8 + grp;
            unsigned bh0 = *(const unsigned*)&Bh[n][kp];
            unsigned bh1 = *(const unsigned*)&Bh[n][kp + 8];
            unsigned bl0 = *(const unsigned*)&Bl[n][kp];
            unsigned bl1 = *(const unsigned*)&Bl[n][kp + 8];
            mma16816(c[nt], ah0, ah1, ah2, ah3, bh0, bh1);
            mma16816(c[nt], ah0, ah1, ah2, ah3, bl0, bl1);
            mma16816(c[nt], al0, al1, al2, al3, bh0, bh1);
        }
    }

    // ---- epilogue: store xl, fused a_src/a_dst ----
    int row0 = rbase + frow;
    int row1 = row0 + 8;
    float as0 = 0.f, ad0 = 0.f, as1 = 0.f, ad1 = 0.f;
    #pragma unroll
    for (int nt = 0; nt < 4; nt++) {
        int ch = nt * 8 + qid * 2;
        float s0 = att_src[ch], s1 = att_src[ch + 1];
        float d0 = att_dst[ch], d1 = att_dst[ch + 1];
        if (row0 < nN)
            *(float2*)&g_xl[(size_t)row0 * CC + ch] =
                make_float2(c[nt][0], c[nt][1]);
        if (row1 < nN)
            *(float2*)&g_xl[(size_t)row1 * CC + ch] =
                make_float2(c[nt][2], c[nt][3]);
        as0 += c[nt][0] * s0 + c[nt][1] * s1;
        ad0 += c[nt][0] * d0 + c[nt][1] * d1;
        as1 += c[nt][2] * s0 + c[nt][3] * s1;
        ad1 += c[nt][2] * d0 + c[nt][3] * d1;
    }
    #pragma unroll
    for (int o = 1; o <= 2; o <<= 1) {
        as0 += __shfl_xor_sync(0xFFFFFFFFu, as0, o);
        ad0 += __shfl_xor_sync(0xFFFFFFFFu, ad0, o);
        as1 += __shfl_xor_sync(0xFFFFFFFFu, as1, o);
        ad1 += __shfl_xor_sync(0xFFFFFFFFu, ad1, o);
    }
    if (qid == 0) {
        if (row0 < nN) { g_asrc[row0] = as0; g_adst[row0] = ad0; }
        if (row1 < nN) { g_asrc[row1] = as1; g_adst[row1] = ad1; }
    }
}

// ---------------- scan (exclusive prefix of deg -> rowptr) ------------------
__global__ void k_scan1(int nN) {
    __shared__ int sh[1024];
    int tid = threadIdx.x;
    int i = blockIdx.x * 1024 + tid;
    int v = (i < nN) ? g_deg[i] : 0;
    sh[tid] = v;
    __syncthreads();
    for (int off = 1; off < 1024; off <<= 1) {
        int t = (tid >= off) ? sh[tid - off] : 0;
        __syncthreads();
        sh[tid] += t;
        __syncthreads();
    }
    if (i < nN) g_scan[i] = sh[tid];
    if (tid == 1023) g_bsum[blockIdx.x] = sh[1023];
}

__global__ void k_scan2(int nb, int nE) {
    int run = 0;
    for (int b = 0; b < nb; b++) {
        int t = g_bsum[b];
        g_boff[b] = run;
        run += t;
    }
    g_scalars[2] = g_scalars[0] / (float)nE;   // mean edge weight
}

// rowptr[i] = edge_scan[i] + i (self-loop slot per node, pre-written here).
__global__ void k_scan3(int nN, int nE) {
    int i = blockIdx.x * blockDim.x + threadIdx.x;
    if (i < nN) {
        int ex = g_scan[i] - g_deg[i] + g_boff[i >> 10] + i;
        g_rowptr[i] = ex;
        g_cursor[i] = ex + 1;
        unsigned long long e = (unsigned long long)(unsigned)i |
            ((unsigned long long)__float_as_uint(g_scalars[2]) << 32);
        g_csr[ex] = e;
    }
    if (i == 0) g_rowptr[nN] = nN + nE;
}

// ---------------- fill CSR with packed (src, edge_weight) -------------------
__global__ void k_fill(const int* __restrict__ ei, const float* __restrict__ ew,
                       int nE) {
    int i = blockIdx.x * blockDim.x + threadIdx.x;
    if (i >= nE) return;
    int s = ei[i];
    int d = ei[nE + i];
    float w = ew[i];
    int pos = atomicAdd(&g_cursor[d], 1);
    unsigned long long e = (unsigned long long)(unsigned)s |
                           ((unsigned long long)__float_as_uint(w) << 32);
    g_csr[pos] = e;
}

// ---------------- gather: softmax-aggregate + fused heads -------------------
__global__ void __launch_bounds__(256)
k_gather(const float* __restrict__ bias_conv,
         const float* __restrict__ Wb, const float* __restrict__ bb,
         const float* __restrict__ Ww, const float* __restrict__ mask,
         float* __restrict__ out, int nN, int nE) {
    int warp = (blockIdx.x * blockDim.x + threadIdx.x) >> 5;
    int lane = threadIdx.x & 31;
    if (warp >= nN) return;
    int beg = g_rowptr[warp];
    int end = g_rowptr[warp + 1];
    float ad = g_adst[warp];
    float ke = g_scalars[1];
    float acc = 0.f, den = 0.f;

    int i = beg;
    for (; i + 4 <= end; i += 4) {
        unsigned long long e0 = g_csr[i];
        unsigned long long e1 = g_csr[i + 1];
        unsigned long long e2 = g_csr[i + 2];
        unsigned long long e3 = g_csr[i + 3];
        int s0 = (int)(unsigned)e0, s1 = (int)(unsigned)e1;
        int s2 = (int)(unsigned)e2, s3 = (int)(unsigned)e3;
        float v0 = g_xl[(size_t)s0 * CC + lane];
        float v1 = g_xl[(size_t)s1 * CC + lane];
        float v2 = g_xl[(size_t)s2 * CC + lane];
        float v3 = g_xl[(size_t)s3 * CC + lane];
        float as0 = g_asrc[s0], as1 = g_asrc[s1];
        float as2 = g_asrc[s2], as3 = g_asrc[s3];
        float a0 = fmaf(ke, __uint_as_float((unsigned)(e0 >> 32)), as0 + ad);
        float a1 = fmaf(ke, __uint_as_float((unsigned)(e1 >> 32)), as1 + ad);
        float a2 = fmaf(ke, __uint_as_float((unsigned)(e2 >> 32)), as2 + ad);
        float a3 = fmaf(ke, __uint_as_float((unsigned)(e3 >> 32)), as3 + ad);
        a0 = (a0 > 0.f) ? a0 : NEG * a0;
        a1 = (a1 > 0.f) ? a1 : NEG * a1;
        a2 = (a2 > 0.f) ? a2 : NEG * a2;
        a3 = (a3 > 0.f) ? a3 : NEG * a3;
        float x0 = __expf(a0), x1 = __expf(a1);
        float x2 = __expf(a2), x3 = __expf(a3);
        den += x0 + x1 + x2 + x3;
        acc = fmaf(x0, v0, acc);
        acc = fmaf(x1, v1, acc);
        acc = fmaf(x2, v2, acc);
        acc = fmaf(x3, v3, acc);
    }
    for (; i < end; i++) {
        unsigned long long e = g_csr[i];
        int s = (int)(unsigned)e;
        float v = g_xl[(size_t)s * CC + lane];
        float a = fmaf(ke, __uint_as_float((unsigned)(e >> 32)), g_asrc[s] + ad);
        a = (a > 0.f) ? a : NEG * a;
        float ex = __expf(a);
        den += ex;
        acc = fmaf(ex, v, acc);
    }

    float h = acc / den + bias_conv[lane];
    h = fmaxf(h, 0.f);
    float bsum = h * Wb[lane];
    float wsum = h * Ww[lane];
    #pragma unroll
    for (int o = 16; o > 0; o >>= 1) {
        bsum += __shfl_xor_sync(0xFFFFFFFFu, bsum, o);
        wsum += __shfl_xor_sync(0xFFFFFFFFu, wsum, o);
    }
    if (lane == 0) {
        g_hw[warp] = wsum;
        out[nE + warp] = (bsum + bb[0]) * mask[warp];
    }
}

// ---------------- edge output: 0.5*(hw[s]+hw[d]) + bw (vectorized) ---------
__global__ void k_edge(const int* __restrict__ ei, const float* __restrict__ bw,
                       float* __restrict__ out, int nE) {
    int q = blockIdx.x * blockDim.x + threadIdx.x;
    int nq = nE >> 2;
    float b = bw[0];
    if (q < nq) {
        int4 s4 = ((const int4*)ei)[q];
        int4 d4 = ((const int4*)(ei + nE))[q];
        float4 o;
        o.x = 0.5f * (g_hw[s4.x] + g_hw[d4.x]) + b;
        o.y = 0.5f * (g_hw[s4.y] + g_hw[d4.y]) + b;
        o.z = 0.5f * (g_hw[s4.z] + g_hw[d4.z]) + b;
        o.w = 0.5f * (g_hw[s4.w] + g_hw[d4.w]) + b;
        ((float4*)out)[q] = o;
    }
    if (q < (nE & 3)) {
        int idx = (nq << 2) + q;
        out[idx] = 0.5f * (g_hw[ei[idx]] + g_hw[ei[nE + idx]]) + b;
    }
}

// ---------------- launch ----------------------------------------------------
extern "C" void kernel_launch(void* const* d_in, const int* in_sizes, int n_in,
                              void* d_out, int out_size) {
    const float* x         = (const float*)d_in[0];
    const int*   ei        = (const int*)d_in[1];
    const float* ew        = (const float*)d_in[2];
    const float* mask      = (const float*)d_in[3];
    const float* W_src     = (const float*)d_in[4];
    const float* att_src   = (const float*)d_in[5];
    const float* att_dst   = (const float*)d_in[6];
    const float* att_edge  = (const float*)d_in[7];
    const float* W_edge    = (const float*)d_in[8];
    const float* bias_conv = (const float*)d_in[9];
    const float* Wb        = (const float*)d_in[10];
    const float* bb        = (const float*)d_in[11];
    const float* Ww        = (const float*)d_in[12];
    const float* bw        = (const float*)d_in[13];
    float* out = (float*)d_out;

    int nN = in_sizes[3];            // input_mask: [N,1]
    int nE = in_sizes[2];            // edge_weight: [E,1]

    int nb = (nN + 1023) / 1024;
    // Order keeps k_gemm in the ncu-profiled slot (4th launch).
    k_init<<<(nN + 255) / 256, 256>>>(W_edge, att_edge, nN);
    k_deg_mean<<<2048, 256>>>(ei, ew, nE);
    k_scan1<<<nb, 1024>>>(nN);
    k_gemm<<<(nN + GROWS - 1) / GROWS, 256>>>(x, W_src, att_src, att_dst, nN);
    k_scan2<<<1, 1>>>(nb, nE);
    k_scan3<<<(nN + 255) / 256, 256>>>(nN, nE);
    k_fill<<<(nE + 255) / 256, 256>>>(ei, ew, nE);
    k_gather<<<(nN + 7) / 8, 256>>>(bias_conv, Wb, bb, Ww, mask, out, nN, nE);
    k_edge<<<((nE >> 2) + 255) / 256, 256>>>(ei, bw, out, nE);
}